// round 16
// baseline (speedup 1.0000x reference)
#include <cuda_runtime.h>
#include <cuda_fp16.h>
#include <math.h>
#include <stdint.h>

// ============================================================================
// MoEGate (DeepSeek-V3 router) for GB300 — round 16
//   logits[T,256] = hidden[T,7168] @ weight[256,7168]^T
//   GEMM: exact round-14 champion (2-stage, BM=BN=128, 512 thr, KC=32, fp16
//   split hi/lo, 3 products fp32-acc, two-level accumulation, weights x512,
//   RSTRIDE=80, ldmatrix.x4, top-of-chunk LDG, end-of-chunk convert+store)
//   + ONE change: odd warps run k-step 1 before k-step 0. This desynchronizes
//   the barrier-aligned LDSM/mma phases across warps so crossbar and tensor
//   pipes overlap instead of alternating.
// Output (float32): [ topk_idx (T*8) ; topk_weight (T*8) ]
// ============================================================================

#define N_EXPERTS 256
#define N_GROUP 8
#define EPG 32
#define TOP_K 8
#define TOPK_GROUP 4
#define MAX_T 8192
#define KDIM 7168

#define WSCALE 512.0f
#define WUNSCALE 0.001953125f   // 1/512, exact

__device__ float g_logits[MAX_T * N_EXPERTS];
__device__ int g_dummy;

#define BM 128
#define BN 128
#define KC 32
#define NCHUNK (KDIM / KC)          // 224
#define RSTRIDE 80                  // bytes per smem row (64B data + 16B pad)
#define TILE_B (128 * RSTRIDE)      // 10240 B
#define STAGE_B (4 * TILE_B)        // 40960 B
#define DSMEM_REQ (2 * STAGE_B)     // 81920 B

__device__ __forceinline__ uint32_t smem_u32(const void* p) {
    uint32_t a;
    asm("{ .reg .u64 t; cvta.to.shared.u64 t, %1; cvt.u32.u64 %0, t; }"
        : "=r"(a) : "l"(p));
    return a;
}

#define LDSM_X4(r0, r1, r2, r3, addr)                                          \
    asm volatile("ldmatrix.sync.aligned.m8n8.x4.shared.b16 {%0,%1,%2,%3}, [%4];" \
        : "=r"(r0), "=r"(r1), "=r"(r2), "=r"(r3) : "r"(addr))

__device__ __forceinline__ void mma_f16(float* c, const uint32_t* a,
                                        const uint32_t* b) {
    asm volatile(
        "mma.sync.aligned.m16n8k16.row.col.f32.f16.f16.f32 "
        "{%0,%1,%2,%3}, {%4,%5,%6,%7}, {%8,%9}, {%0,%1,%2,%3};"
        : "+f"(c[0]), "+f"(c[1]), "+f"(c[2]), "+f"(c[3])
        : "r"(a[0]), "r"(a[1]), "r"(a[2]), "r"(a[3]), "r"(b[0]), "r"(b[1]));
}

__device__ __forceinline__ uint32_t pack2_hi(float x, float y) {
    __half2 h = __float22half2_rn(make_float2(x, y));
    return *(uint32_t*)&h;
}
__device__ __forceinline__ uint32_t pack2_lo(float x, float y) {
    __half2 h = __float22half2_rn(make_float2(x, y));
    float2 hf = __half22float2(h);
    __half2 l = __float22half2_rn(make_float2(x - hf.x, y - hf.y));
    return *(uint32_t*)&l;
}

__device__ __forceinline__ void cvt_store2(char* hi, char* lo, uint32_t off,
                                           float4 v0, float4 v1) {
    uint4 h = make_uint4(pack2_hi(v0.x, v0.y), pack2_hi(v0.z, v0.w),
                         pack2_hi(v1.x, v1.y), pack2_hi(v1.z, v1.w));
    uint4 l = make_uint4(pack2_lo(v0.x, v0.y), pack2_lo(v0.z, v0.w),
                         pack2_lo(v1.x, v1.y), pack2_lo(v1.z, v1.w));
    *(uint4*)(hi + off) = h;
    *(uint4*)(lo + off) = l;
}

__global__ void __launch_bounds__(512, 1)
gemm_mma_kernel(const float* __restrict__ A, const float* __restrict__ B, int T)
{
    extern __shared__ char smem[];
    const uint32_t sbase = smem_u32(smem);

    const int tid  = threadIdx.x;
    const int wid  = tid >> 5;
    const int lane = tid & 31;
    const int bn = blockIdx.x * BN;
    const int bm = blockIdx.y * BM;

    const int wm = wid >> 2;           // 0..3 -> m offset 32*wm
    const int wn = wid & 3;            // 0..3 -> n offset 32*wn
    const uint32_t ksxor = (uint32_t)(wid & 1);  // odd warps: ks1 first

    const uint32_t lrow16 = (uint32_t)(lane & 15);
    const uint32_t lkoff  = (uint32_t)((lane >> 4) * 16);
    const uint32_t aRow = (uint32_t)(wm * 32 + lrow16) * RSTRIDE + lkoff;
    const uint32_t bRow = (uint32_t)(wn * 32 + lrow16) * RSTRIDE + lkoff;

    const int lrowL = tid >> 2;
    const int lq    = tid & 3;
    const float* Ag = A + (size_t)(bm + lrowL) * KDIM + lq * 8;
    const float* Bg = B + (size_t)(bn + lrowL) * KDIM + lq * 8;
    const uint32_t sto = (uint32_t)(lrowL * RSTRIDE + lq * 16);

    float accH[2][4][4], accL[2][4][4];
#pragma unroll
    for (int i = 0; i < 2; i++)
#pragma unroll
        for (int j = 0; j < 4; j++)
#pragma unroll
            for (int q = 0; q < 4; q++) { accH[i][j][q] = 0.0f; accL[i][j][q] = 0.0f; }

    // ---- prologue: chunk 0 -> stage 0 ----
    {
        float4 a0 = *(const float4*)(Ag);
        float4 a1 = *(const float4*)(Ag + 4);
        float4 b0 = *(const float4*)(Bg);
        float4 b1 = *(const float4*)(Bg + 4);
        b0.x *= WSCALE; b0.y *= WSCALE; b0.z *= WSCALE; b0.w *= WSCALE;
        b1.x *= WSCALE; b1.y *= WSCALE; b1.z *= WSCALE; b1.w *= WSCALE;
        cvt_store2(smem,              smem + TILE_B,     sto, a0, a1);
        cvt_store2(smem + 2 * TILE_B, smem + 3 * TILE_B, sto, b0, b1);
    }
    __syncthreads();

    for (int i = 0; i < NCHUNK; i++) {
        const int b = i & 1;
        const uint32_t st = sbase + (uint32_t)b * STAGE_B;
        const uint32_t sAhi = st;
        const uint32_t sAlo = st + TILE_B;
        const uint32_t sBhi = st + 2 * TILE_B;
        const uint32_t sBlo = st + 3 * TILE_B;

        // prefetch next chunk into registers (both A and B, at chunk top)
        float4 ar0, ar1, br0, br1;
        const bool more = (i + 1 < NCHUNK);
        if (more) {
            const size_t k0 = (size_t)(i + 1) * KC;
            ar0 = *(const float4*)(Ag + k0);
            ar1 = *(const float4*)(Ag + k0 + 4);
            br0 = *(const float4*)(Bg + k0);
            br1 = *(const float4*)(Bg + k0 + 4);
        }

        // compute: 2 k-steps x 3 products x 8 mma; odd warps reverse k-step
        // order (kb = (ks ^ ksxor)*32) to desynchronize LDSM/mma phases.
#pragma unroll
        for (int ks = 0; ks < 2; ks++) {
            const uint32_t kb = (uint32_t)(ks ^ (int)ksxor) * 32;
            uint32_t afr[2][4], bhi[4][2], blo[4][2];

#pragma unroll
            for (int mt = 0; mt < 2; mt++)
                LDSM_X4(afr[mt][0], afr[mt][1], afr[mt][2], afr[mt][3],
                        sAhi + aRow + (uint32_t)(mt * 16) * RSTRIDE + kb);
#pragma unroll
            for (int p = 0; p < 2; p++) {
                uint32_t t0, t1, t2, t3;
                LDSM_X4(t0, t1, t2, t3,
                        sBhi + bRow + (uint32_t)(p * 16) * RSTRIDE + kb);
                bhi[2*p][0] = t0;   bhi[2*p][1] = t2;
                bhi[2*p+1][0] = t1; bhi[2*p+1][1] = t3;
            }
#pragma unroll
            for (int mt = 0; mt < 2; mt++)
#pragma unroll
                for (int nt = 0; nt < 4; nt++)
                    mma_f16(accL[mt][nt], afr[mt], bhi[nt]);

#pragma unroll
            for (int p = 0; p < 2; p++) {
                uint32_t t0, t1, t2, t3;
                LDSM_X4(t0, t1, t2, t3,
                        sBlo + bRow + (uint32_t)(p * 16) * RSTRIDE + kb);
                blo[2*p][0] = t0;   blo[2*p][1] = t2;
                blo[2*p+1][0] = t1; blo[2*p+1][1] = t3;
            }
#pragma unroll
            for (int mt = 0; mt < 2; mt++)
#pragma unroll
                for (int nt = 0; nt < 4; nt++)
                    mma_f16(accL[mt][nt], afr[mt], blo[nt]);

#pragma unroll
            for (int mt = 0; mt < 2; mt++)
                LDSM_X4(afr[mt][0], afr[mt][1], afr[mt][2], afr[mt][3],
                        sAlo + aRow + (uint32_t)(mt * 16) * RSTRIDE + kb);
#pragma unroll
            for (int mt = 0; mt < 2; mt++)
#pragma unroll
                for (int nt = 0; nt < 4; nt++)
                    mma_f16(accL[mt][nt], afr[mt], bhi[nt]);
        }

        // fold local -> main every 8 chunks (224 % 8 == 0)
        if ((i & 7) == 7) {
#pragma unroll
            for (int mt = 0; mt < 2; mt++)
#pragma unroll
                for (int nt = 0; nt < 4; nt++)
#pragma unroll
                    for (int q = 0; q < 4; q++) {
                        accH[mt][nt][q] += accL[mt][nt][q];
                        accL[mt][nt][q] = 0.0f;
                    }
        }

        // convert + store next chunk into other stage (both A and B, at end)
        if (more) {
            char* nst = smem + (b ^ 1) * STAGE_B;
            br0.x *= WSCALE; br0.y *= WSCALE; br0.z *= WSCALE; br0.w *= WSCALE;
            br1.x *= WSCALE; br1.y *= WSCALE; br1.z *= WSCALE; br1.w *= WSCALE;
            cvt_store2(nst,              nst + TILE_B,     sto, ar0, ar1);
            cvt_store2(nst + 2 * TILE_B, nst + 3 * TILE_B, sto, br0, br1);
        }
        __syncthreads();
    }

    // ---- epilogue: unscale by 1/512 and write logits ----
    const int lg = lane >> 2;
    const int tg = lane & 3;
#pragma unroll
    for (int mt = 0; mt < 2; mt++) {
#pragma unroll
        for (int nt = 0; nt < 4; nt++) {
            int row0 = bm + wm * 32 + mt * 16 + lg;
            int col  = bn + wn * 32 + nt * 8 + tg * 2;
            float* d0 = g_logits + (size_t)row0 * N_EXPERTS + col;
            float* d1 = g_logits + (size_t)(row0 + 8) * N_EXPERTS + col;
            *(float2*)d0 = make_float2(accH[mt][nt][0] * WUNSCALE,
                                       accH[mt][nt][1] * WUNSCALE);
            *(float2*)d1 = make_float2(accH[mt][nt][2] * WUNSCALE,
                                       accH[mt][nt][3] * WUNSCALE);
        }
    }
}

// ---------------------------------------------------------------------------
// Gating: one warp per token. Group top-2 via per-lane top2 + bfly merge.
// ---------------------------------------------------------------------------
__device__ __forceinline__ void argmax_red(float& v, int& i)
{
#pragma unroll
    for (int o = 16; o > 0; o >>= 1) {
        float v2 = __shfl_down_sync(0xffffffffu, v, o);
        int   i2 = __shfl_down_sync(0xffffffffu, i, o);
        if (v2 > v || (v2 == v && i2 < i)) { v = v2; i = i2; }
    }
    v = __shfl_sync(0xffffffffu, v, 0);
    i = __shfl_sync(0xffffffffu, i, 0);
}

__global__ void __launch_bounds__(256)
gate_kernel(const float* __restrict__ bias, float* __restrict__ out,
            int T, int out_size)
{
    __shared__ float ss[8][N_EXPERTS];
    __shared__ float bs[N_EXPERTS];

    const int tid  = threadIdx.x;
    const int warp = tid >> 5;
    const int lane = tid & 31;
    const int t = blockIdx.x * 8 + warp;

    if (tid < N_EXPERTS) bs[tid] = bias[tid];

    float* s = ss[warp];
    if (t < T) {
        const float* lg = g_logits + (size_t)t * N_EXPERTS;
#pragma unroll
        for (int j = 0; j < 8; j++) {
            int e = j * 32 + lane;
            float x = lg[e];
            s[e] = 1.0f / (1.0f + expf(-x));
        }
    }
    __syncthreads();
    if (t >= T) return;

    // group scores: per-lane top2 over its 8 experts, merge over quartet
    float v1 = -INFINITY, v2 = -INFINITY;
#pragma unroll
    for (int j = 0; j < 8; j++) {
        int e = (lane << 3) + j;
        float val = s[e] + bs[e];
        if (val > v1)      { v2 = v1; v1 = val; }
        else if (val > v2) { v2 = val; }
    }
#pragma unroll
    for (int o = 1; o <= 2; o <<= 1) {
        float u1 = __shfl_xor_sync(0xffffffffu, v1, o);
        float u2 = __shfl_xor_sync(0xffffffffu, v2, o);
        float nv1 = fmaxf(v1, u1);
        float nv2 = fmaxf(fminf(v1, u1), fmaxf(v2, u2));
        v1 = nv1; v2 = nv2;
    }
    float gsum = v1 + v2;

    float gv[N_GROUP];
#pragma unroll
    for (int j = 0; j < N_GROUP; j++)
        gv[j] = __shfl_sync(0xffffffffu, gsum, j * 4);

    unsigned gmask = 0;
#pragma unroll
    for (int r = 0; r < TOPK_GROUP; r++) {
        float best = -INFINITY; int bi = 0;
#pragma unroll
        for (int j = 0; j < N_GROUP; j++) {
            if (!((gmask >> j) & 1u) && gv[j] > best) { best = gv[j]; bi = j; }
        }
        gmask |= 1u << bi;
    }

    const bool gok = (gmask >> (lane >> 2)) & 1u;
    unsigned sel = 0;
    int   out_e = 0;
    float out_w = 0.0f;

#pragma unroll
    for (int r = 0; r < TOP_K; r++) {
        float v = -INFINITY; int ie = N_EXPERTS;
        if (gok) {
#pragma unroll
            for (int j = 0; j < 8; j++) {
                if (!((sel >> j) & 1u)) {
                    int e = lane * 8 + j;
                    float val = s[e] + bs[e];
                    if (val > v) { v = val; ie = e; }
                }
            }
        }
        argmax_red(v, ie);
        if ((ie >> 3) == lane) sel |= 1u << (ie & 7);
        if (lane == r) { out_e = ie; out_w = s[ie]; }
    }

    float wsum = (lane < TOP_K) ? out_w : 0.0f;
#pragma unroll
    for (int o = 16; o > 0; o >>= 1)
        wsum += __shfl_down_sync(0xffffffffu, wsum, o);
    wsum = __shfl_sync(0xffffffffu, wsum, 0);

    if (lane < TOP_K) {
        float denom = wsum + 1e-20f;
        float wn = out_w / denom * 2.5f;
        if (out_size >= 2 * T * TOP_K) {
            out[(size_t)t * TOP_K + lane] = (float)out_e;
            out[(size_t)T * TOP_K + (size_t)t * TOP_K + lane] = wn;
        } else {
            out[(size_t)t * TOP_K + lane] = wn;
        }
    }
}

// trivial kernel: 3 launches/call so capture index 9 lands on the GEMM
__global__ void dummy_kernel() {
    if (threadIdx.x == 0) g_dummy = 1;
}

// ---------------------------------------------------------------------------
extern "C" void kernel_launch(void* const* d_in, const int* in_sizes, int n_in,
                              void* d_out, int out_size)
{
    const float* hidden = (const float*)d_in[0];
    const float* weight = (const float*)d_in[1];
    const float* bias   = (const float*)d_in[2];
    float* out = (float*)d_out;

    const int H = in_sizes[1] / N_EXPERTS;   // 7168
    const int T = in_sizes[0] / H;           // 8192

    static bool attr_set = false;
    if (!attr_set) {
        cudaFuncSetAttribute(gemm_mma_kernel,
                             cudaFuncAttributeMaxDynamicSharedMemorySize,
                             DSMEM_REQ);
        attr_set = true;
    }

    dim3 ggrid(N_EXPERTS / BN, (T + BM - 1) / BM);   // (2, 64)
    gemm_mma_kernel<<<ggrid, 512, DSMEM_REQ>>>(hidden, weight, T);

    int nblk = (T + 7) / 8;
    gate_kernel<<<nblk, 256>>>(bias, out, T, out_size);

    dummy_kernel<<<1, 32>>>();
}

// round 17
// speedup vs baseline: 1.0356x; 1.0356x over previous
#include <cuda_runtime.h>
#include <cuda_fp16.h>
#include <math.h>
#include <stdint.h>

// ============================================================================
// MoEGate (DeepSeek-V3 router) for GB300 — round 17
//   logits[T,256] = hidden[T,7168] @ weight[256,7168]^T
//   GEMM: round-14 champion (2-stage, BM=BN=128, 512 thr, KC=32, fp16 split
//   hi/lo, 3 products fp32-acc, two-level accumulation, weights x512,
//   RSTRIDE=80, ldmatrix.x4, top-of-chunk LDG, end-of-chunk convert+store)
//   + ONE scheduling change: B-lo LDSM wave hoisted above mma group 1
//   (register-neutral, same accumulation order) so group 2 never waits on a
//   freshly-issued LDSM wave. Dummy kernel removed (-3.6 us).
// Output (float32): [ topk_idx (T*8) ; topk_weight (T*8) ]
// ============================================================================

#define N_EXPERTS 256
#define N_GROUP 8
#define EPG 32
#define TOP_K 8
#define TOPK_GROUP 4
#define MAX_T 8192
#define KDIM 7168

#define WSCALE 512.0f
#define WUNSCALE 0.001953125f   // 1/512, exact

__device__ float g_logits[MAX_T * N_EXPERTS];

#define BM 128
#define BN 128
#define KC 32
#define NCHUNK (KDIM / KC)          // 224
#define RSTRIDE 80                  // bytes per smem row (64B data + 16B pad)
#define TILE_B (128 * RSTRIDE)      // 10240 B
#define STAGE_B (4 * TILE_B)        // 40960 B
#define DSMEM_REQ (2 * STAGE_B)     // 81920 B

__device__ __forceinline__ uint32_t smem_u32(const void* p) {
    uint32_t a;
    asm("{ .reg .u64 t; cvta.to.shared.u64 t, %1; cvt.u32.u64 %0, t; }"
        : "=r"(a) : "l"(p));
    return a;
}

#define LDSM_X4(r0, r1, r2, r3, addr)                                          \
    asm volatile("ldmatrix.sync.aligned.m8n8.x4.shared.b16 {%0,%1,%2,%3}, [%4];" \
        : "=r"(r0), "=r"(r1), "=r"(r2), "=r"(r3) : "r"(addr))

__device__ __forceinline__ void mma_f16(float* c, const uint32_t* a,
                                        const uint32_t* b) {
    asm volatile(
        "mma.sync.aligned.m16n8k16.row.col.f32.f16.f16.f32 "
        "{%0,%1,%2,%3}, {%4,%5,%6,%7}, {%8,%9}, {%0,%1,%2,%3};"
        : "+f"(c[0]), "+f"(c[1]), "+f"(c[2]), "+f"(c[3])
        : "r"(a[0]), "r"(a[1]), "r"(a[2]), "r"(a[3]), "r"(b[0]), "r"(b[1]));
}

__device__ __forceinline__ uint32_t pack2_hi(float x, float y) {
    __half2 h = __float22half2_rn(make_float2(x, y));
    return *(uint32_t*)&h;
}
__device__ __forceinline__ uint32_t pack2_lo(float x, float y) {
    __half2 h = __float22half2_rn(make_float2(x, y));
    float2 hf = __half22float2(h);
    __half2 l = __float22half2_rn(make_float2(x - hf.x, y - hf.y));
    return *(uint32_t*)&l;
}

__device__ __forceinline__ void cvt_store2(char* hi, char* lo, uint32_t off,
                                           float4 v0, float4 v1) {
    uint4 h = make_uint4(pack2_hi(v0.x, v0.y), pack2_hi(v0.z, v0.w),
                         pack2_hi(v1.x, v1.y), pack2_hi(v1.z, v1.w));
    uint4 l = make_uint4(pack2_lo(v0.x, v0.y), pack2_lo(v0.z, v0.w),
                         pack2_lo(v1.x, v1.y), pack2_lo(v1.z, v1.w));
    *(uint4*)(hi + off) = h;
    *(uint4*)(lo + off) = l;
}

__global__ void __launch_bounds__(512, 1)
gemm_mma_kernel(const float* __restrict__ A, const float* __restrict__ B, int T)
{
    extern __shared__ char smem[];
    const uint32_t sbase = smem_u32(smem);

    const int tid  = threadIdx.x;
    const int wid  = tid >> 5;
    const int lane = tid & 31;
    const int bn = blockIdx.x * BN;
    const int bm = blockIdx.y * BM;

    const int wm = wid >> 2;           // 0..3 -> m offset 32*wm
    const int wn = wid & 3;            // 0..3 -> n offset 32*wn

    const uint32_t lrow16 = (uint32_t)(lane & 15);
    const uint32_t lkoff  = (uint32_t)((lane >> 4) * 16);
    const uint32_t aRow = (uint32_t)(wm * 32 + lrow16) * RSTRIDE + lkoff;
    const uint32_t bRow = (uint32_t)(wn * 32 + lrow16) * RSTRIDE + lkoff;

    const int lrowL = tid >> 2;
    const int lq    = tid & 3;
    const float* Ag = A + (size_t)(bm + lrowL) * KDIM + lq * 8;
    const float* Bg = B + (size_t)(bn + lrowL) * KDIM + lq * 8;
    const uint32_t sto = (uint32_t)(lrowL * RSTRIDE + lq * 16);

    float accH[2][4][4], accL[2][4][4];
#pragma unroll
    for (int i = 0; i < 2; i++)
#pragma unroll
        for (int j = 0; j < 4; j++)
#pragma unroll
            for (int q = 0; q < 4; q++) { accH[i][j][q] = 0.0f; accL[i][j][q] = 0.0f; }

    // ---- prologue: chunk 0 -> stage 0 ----
    {
        float4 a0 = *(const float4*)(Ag);
        float4 a1 = *(const float4*)(Ag + 4);
        float4 b0 = *(const float4*)(Bg);
        float4 b1 = *(const float4*)(Bg + 4);
        b0.x *= WSCALE; b0.y *= WSCALE; b0.z *= WSCALE; b0.w *= WSCALE;
        b1.x *= WSCALE; b1.y *= WSCALE; b1.z *= WSCALE; b1.w *= WSCALE;
        cvt_store2(smem,              smem + TILE_B,     sto, a0, a1);
        cvt_store2(smem + 2 * TILE_B, smem + 3 * TILE_B, sto, b0, b1);
    }
    __syncthreads();

    for (int i = 0; i < NCHUNK; i++) {
        const int b = i & 1;
        const uint32_t st = sbase + (uint32_t)b * STAGE_B;
        const uint32_t sAhi = st;
        const uint32_t sAlo = st + TILE_B;
        const uint32_t sBhi = st + 2 * TILE_B;
        const uint32_t sBlo = st + 3 * TILE_B;

        // prefetch next chunk into registers (both A and B, at chunk top)
        float4 ar0, ar1, br0, br1;
        const bool more = (i + 1 < NCHUNK);
        if (more) {
            const size_t k0 = (size_t)(i + 1) * KC;
            ar0 = *(const float4*)(Ag + k0);
            ar1 = *(const float4*)(Ag + k0 + 4);
            br0 = *(const float4*)(Bg + k0);
            br1 = *(const float4*)(Bg + k0 + 4);
        }

        // compute: 2 k-steps x 3 products x 8 mma.
        // R17 change: B-lo LDSM issued BEFORE mma group 1 (peak frag regs
        // unchanged at 24), so groups 1-2 run back-to-back.
#pragma unroll
        for (int ks = 0; ks < 2; ks++) {
            const uint32_t kb = ks * 32;
            uint32_t afr[2][4], bhi[4][2], blo[4][2];

            // LDSM wave: A-hi, B-hi, B-lo (all before any mma)
#pragma unroll
            for (int mt = 0; mt < 2; mt++)
                LDSM_X4(afr[mt][0], afr[mt][1], afr[mt][2], afr[mt][3],
                        sAhi + aRow + (uint32_t)(mt * 16) * RSTRIDE + kb);
#pragma unroll
            for (int p = 0; p < 2; p++) {
                uint32_t t0, t1, t2, t3;
                LDSM_X4(t0, t1, t2, t3,
                        sBhi + bRow + (uint32_t)(p * 16) * RSTRIDE + kb);
                bhi[2*p][0] = t0;   bhi[2*p][1] = t2;
                bhi[2*p+1][0] = t1; bhi[2*p+1][1] = t3;
            }
#pragma unroll
            for (int p = 0; p < 2; p++) {
                uint32_t t0, t1, t2, t3;
                LDSM_X4(t0, t1, t2, t3,
                        sBlo + bRow + (uint32_t)(p * 16) * RSTRIDE + kb);
                blo[2*p][0] = t0;   blo[2*p][1] = t2;
                blo[2*p+1][0] = t1; blo[2*p+1][1] = t3;
            }

            // mma group 1: Ahi * Bhi
#pragma unroll
            for (int mt = 0; mt < 2; mt++)
#pragma unroll
                for (int nt = 0; nt < 4; nt++)
                    mma_f16(accL[mt][nt], afr[mt], bhi[nt]);

            // mma group 2: Ahi * Blo (blo already resident)
#pragma unroll
            for (int mt = 0; mt < 2; mt++)
#pragma unroll
                for (int nt = 0; nt < 4; nt++)
                    mma_f16(accL[mt][nt], afr[mt], blo[nt]);

            // A-lo (reuse afr regs), then mma group 3: Alo * Bhi
#pragma unroll
            for (int mt = 0; mt < 2; mt++)
                LDSM_X4(afr[mt][0], afr[mt][1], afr[mt][2], afr[mt][3],
                        sAlo + aRow + (uint32_t)(mt * 16) * RSTRIDE + kb);
#pragma unroll
            for (int mt = 0; mt < 2; mt++)
#pragma unroll
                for (int nt = 0; nt < 4; nt++)
                    mma_f16(accL[mt][nt], afr[mt], bhi[nt]);
        }

        // fold local -> main every 8 chunks (224 % 8 == 0)
        if ((i & 7) == 7) {
#pragma unroll
            for (int mt = 0; mt < 2; mt++)
#pragma unroll
                for (int nt = 0; nt < 4; nt++)
#pragma unroll
                    for (int q = 0; q < 4; q++) {
                        accH[mt][nt][q] += accL[mt][nt][q];
                        accL[mt][nt][q] = 0.0f;
                    }
        }

        // convert + store next chunk into other stage (both A and B, at end)
        if (more) {
            char* nst = smem + (b ^ 1) * STAGE_B;
            br0.x *= WSCALE; br0.y *= WSCALE; br0.z *= WSCALE; br0.w *= WSCALE;
            br1.x *= WSCALE; br1.y *= WSCALE; br1.z *= WSCALE; br1.w *= WSCALE;
            cvt_store2(nst,              nst + TILE_B,     sto, ar0, ar1);
            cvt_store2(nst + 2 * TILE_B, nst + 3 * TILE_B, sto, br0, br1);
        }
        __syncthreads();
    }

    // ---- epilogue: unscale by 1/512 and write logits ----
    const int lg = lane >> 2;
    const int tg = lane & 3;
#pragma unroll
    for (int mt = 0; mt < 2; mt++) {
#pragma unroll
        for (int nt = 0; nt < 4; nt++) {
            int row0 = bm + wm * 32 + mt * 16 + lg;
            int col  = bn + wn * 32 + nt * 8 + tg * 2;
            float* d0 = g_logits + (size_t)row0 * N_EXPERTS + col;
            float* d1 = g_logits + (size_t)(row0 + 8) * N_EXPERTS + col;
            *(float2*)d0 = make_float2(accH[mt][nt][0] * WUNSCALE,
                                       accH[mt][nt][1] * WUNSCALE);
            *(float2*)d1 = make_float2(accH[mt][nt][2] * WUNSCALE,
                                       accH[mt][nt][3] * WUNSCALE);
        }
    }
}

// ---------------------------------------------------------------------------
// Gating: one warp per token. Group top-2 via per-lane top2 + bfly merge.
// ---------------------------------------------------------------------------
__device__ __forceinline__ void argmax_red(float& v, int& i)
{
#pragma unroll
    for (int o = 16; o > 0; o >>= 1) {
        float v2 = __shfl_down_sync(0xffffffffu, v, o);
        int   i2 = __shfl_down_sync(0xffffffffu, i, o);
        if (v2 > v || (v2 == v && i2 < i)) { v = v2; i = i2; }
    }
    v = __shfl_sync(0xffffffffu, v, 0);
    i = __shfl_sync(0xffffffffu, i, 0);
}

__global__ void __launch_bounds__(256)
gate_kernel(const float* __restrict__ bias, float* __restrict__ out,
            int T, int out_size)
{
    __shared__ float ss[8][N_EXPERTS];
    __shared__ float bs[N_EXPERTS];

    const int tid  = threadIdx.x;
    const int warp = tid >> 5;
    const int lane = tid & 31;
    const int t = blockIdx.x * 8 + warp;

    if (tid < N_EXPERTS) bs[tid] = bias[tid];

    float* s = ss[warp];
    if (t < T) {
        const float* lg = g_logits + (size_t)t * N_EXPERTS;
#pragma unroll
        for (int j = 0; j < 8; j++) {
            int e = j * 32 + lane;
            float x = lg[e];
            s[e] = 1.0f / (1.0f + expf(-x));
        }
    }
    __syncthreads();
    if (t >= T) return;

    // group scores: per-lane top2 over its 8 experts, merge over quartet
    float v1 = -INFINITY, v2 = -INFINITY;
#pragma unroll
    for (int j = 0; j < 8; j++) {
        int e = (lane << 3) + j;
        float val = s[e] + bs[e];
        if (val > v1)      { v2 = v1; v1 = val; }
        else if (val > v2) { v2 = val; }
    }
#pragma unroll
    for (int o = 1; o <= 2; o <<= 1) {
        float u1 = __shfl_xor_sync(0xffffffffu, v1, o);
        float u2 = __shfl_xor_sync(0xffffffffu, v2, o);
        float nv1 = fmaxf(v1, u1);
        float nv2 = fmaxf(fminf(v1, u1), fmaxf(v2, u2));
        v1 = nv1; v2 = nv2;
    }
    float gsum = v1 + v2;

    float gv[N_GROUP];
#pragma unroll
    for (int j = 0; j < N_GROUP; j++)
        gv[j] = __shfl_sync(0xffffffffu, gsum, j * 4);

    unsigned gmask = 0;
#pragma unroll
    for (int r = 0; r < TOPK_GROUP; r++) {
        float best = -INFINITY; int bi = 0;
#pragma unroll
        for (int j = 0; j < N_GROUP; j++) {
            if (!((gmask >> j) & 1u) && gv[j] > best) { best = gv[j]; bi = j; }
        }
        gmask |= 1u << bi;
    }

    const bool gok = (gmask >> (lane >> 2)) & 1u;
    unsigned sel = 0;
    int   out_e = 0;
    float out_w = 0.0f;

#pragma unroll
    for (int r = 0; r < TOP_K; r++) {
        float v = -INFINITY; int ie = N_EXPERTS;
        if (gok) {
#pragma unroll
            for (int j = 0; j < 8; j++) {
                if (!((sel >> j) & 1u)) {
                    int e = lane * 8 + j;
                    float val = s[e] + bs[e];
                    if (val > v) { v = val; ie = e; }
                }
            }
        }
        argmax_red(v, ie);
        if ((ie >> 3) == lane) sel |= 1u << (ie & 7);
        if (lane == r) { out_e = ie; out_w = s[ie]; }
    }

    float wsum = (lane < TOP_K) ? out_w : 0.0f;
#pragma unroll
    for (int o = 16; o > 0; o >>= 1)
        wsum += __shfl_down_sync(0xffffffffu, wsum, o);
    wsum = __shfl_sync(0xffffffffu, wsum, 0);

    if (lane < TOP_K) {
        float denom = wsum + 1e-20f;
        float wn = out_w / denom * 2.5f;
        if (out_size >= 2 * T * TOP_K) {
            out[(size_t)t * TOP_K + lane] = (float)out_e;
            out[(size_t)T * TOP_K + (size_t)t * TOP_K + lane] = wn;
        } else {
            out[(size_t)t * TOP_K + lane] = wn;
        }
    }
}

// ---------------------------------------------------------------------------
extern "C" void kernel_launch(void* const* d_in, const int* in_sizes, int n_in,
                              void* d_out, int out_size)
{
    const float* hidden = (const float*)d_in[0];
    const float* weight = (const float*)d_in[1];
    const float* bias   = (const float*)d_in[2];
    float* out = (float*)d_out;

    const int H = in_sizes[1] / N_EXPERTS;   // 7168
    const int T = in_sizes[0] / H;           // 8192

    static bool attr_set = false;
    if (!attr_set) {
        cudaFuncSetAttribute(gemm_mma_kernel,
                             cudaFuncAttributeMaxDynamicSharedMemorySize,
                             DSMEM_REQ);
        attr_set = true;
    }

    dim3 ggrid(N_EXPERTS / BN, (T + BM - 1) / BM);   // (2, 64)
    gemm_mma_kernel<<<ggrid, 512, DSMEM_REQ>>>(hidden, weight, T);

    int nblk = (T + 7) / 8;
    gate_kernel<<<nblk, 256>>>(bias, out, T, out_size);
}